// round 2
// baseline (speedup 1.0000x reference)
#include <cuda_runtime.h>
#include <cstdint>

#define BATCH 8
#define NVAL  261888
#define PRE   6000
#define CAP   8192
#define NW    188          // ceil(6000/32)
#define PROP  1000

// ---------------- scratch (static device globals; no allocation) ----------------
__device__ unsigned           g_u[BATCH * NVAL];          // flipped score bits
__device__ unsigned           g_hist1[BATCH * 65536];
__device__ unsigned           g_hist2[BATCH * 65536];
__device__ unsigned           g_b1[BATCH];
__device__ unsigned           g_above1[BATCH];
__device__ unsigned           g_thresh[BATCH];
__device__ int                g_candcnt[BATCH];
__device__ unsigned long long g_cand[BATCH * CAP];
__device__ float              g_boxes[BATCH * PRE * 4];
__device__ float              g_scores[BATCH * PRE];

// monotone float->uint mapping
__device__ __forceinline__ unsigned flip_f(float f) {
    unsigned b = __float_as_uint(f);
    unsigned mask = (unsigned)((int)b >> 31) | 0x80000000u;
    return b ^ mask;
}
__device__ __forceinline__ float unflip_f(unsigned u) {
    unsigned mask = (u >> 31) ? 0x80000000u : 0xFFFFFFFFu;
    return __uint_as_float(u ^ mask);
}

// ---------------- K0: zero scratch ----------------
__global__ void k_zero() {
    int total = BATCH * 65536;
    for (int i = blockIdx.x * blockDim.x + threadIdx.x; i < total;
         i += gridDim.x * blockDim.x) {
        g_hist1[i] = 0;
        g_hist2[i] = 0;
    }
    if (blockIdx.x == 0 && threadIdx.x < BATCH) g_candcnt[threadIdx.x] = 0;
}

// ---------------- K1: flip scores, hist of high 16 bits ----------------
__global__ void k_score_hist(const float* __restrict__ probs) {
    int b = blockIdx.y;
    for (int n = blockIdx.x * blockDim.x + threadIdx.x; n < NVAL;
         n += gridDim.x * blockDim.x) {
        float s = probs[(b * NVAL + n) * 2 + 1];
        unsigned u = flip_f(s);
        g_u[b * NVAL + n] = u;
        atomicAdd(&g_hist1[b * 65536 + (u >> 16)], 1u);
    }
}

// ---------------- K2: find high-16 bin containing rank PRE ----------------
__global__ void k_findbin1() {
    __shared__ unsigned part[256];
    int b = blockIdx.x;
    const unsigned* hist = g_hist1 + b * 65536;
    unsigned s = 0;
    int base = threadIdx.x * 256;
    for (int i = 0; i < 256; ++i) s += hist[base + i];
    part[threadIdx.x] = s;
    __syncthreads();
    if (threadIdx.x == 0) {
        unsigned acc = 0;
        for (int t = 255; t >= 0; --t) {
            if (acc + part[t] >= (unsigned)PRE) {
                // descend within this chunk
                for (int bin = t * 256 + 255; bin >= t * 256; --bin) {
                    unsigned h = hist[bin];
                    if (acc + h >= (unsigned)PRE) {
                        g_b1[b] = (unsigned)bin;
                        g_above1[b] = acc;  // count strictly above bin
                        return;
                    }
                    acc += h;
                }
            }
            acc += part[t];
        }
        // fallback (shouldn't happen)
        g_b1[b] = 0; g_above1[b] = 0;
    }
}

// ---------------- K3: hist of low 16 bits within bin b1 ----------------
__global__ void k_hist2() {
    int b = blockIdx.y;
    unsigned b1 = g_b1[b];
    for (int n = blockIdx.x * blockDim.x + threadIdx.x; n < NVAL;
         n += gridDim.x * blockDim.x) {
        unsigned u = g_u[b * NVAL + n];
        if ((u >> 16) == b1)
            atomicAdd(&g_hist2[b * 65536 + (u & 0xFFFFu)], 1u);
    }
}

// ---------------- K4: exact 32-bit threshold ----------------
__global__ void k_findbin2() {
    __shared__ unsigned part[256];
    int b = blockIdx.x;
    const unsigned* hist = g_hist2 + b * 65536;
    unsigned K = (unsigned)PRE - g_above1[b];   // >= 1
    unsigned s = 0;
    int base = threadIdx.x * 256;
    for (int i = 0; i < 256; ++i) s += hist[base + i];
    part[threadIdx.x] = s;
    __syncthreads();
    if (threadIdx.x == 0) {
        unsigned acc = 0;
        unsigned b2 = 0;
        for (int t = 255; t >= 0; --t) {
            if (acc + part[t] >= K) {
                for (int bin = t * 256 + 255; bin >= t * 256; --bin) {
                    unsigned h = hist[bin];
                    if (acc + h >= K) { b2 = (unsigned)bin; goto done; }
                    acc += h;
                }
            }
            acc += part[t];
        }
done:
        g_thresh[b] = (g_b1[b] << 16) | b2;
    }
}

// ---------------- K5: compact candidates (u >= T) ----------------
__global__ void k_compact() {
    int b = blockIdx.y;
    unsigned T = g_thresh[b];
    for (int n = blockIdx.x * blockDim.x + threadIdx.x; n < NVAL;
         n += gridDim.x * blockDim.x) {
        unsigned u = g_u[b * NVAL + n];
        if (u >= T) {
            int pos = atomicAdd(&g_candcnt[b], 1);
            if (pos < CAP)
                g_cand[b * CAP + pos] =
                    ((unsigned long long)u << 32) | (unsigned)(~(unsigned)n);
        }
    }
}

// ---------------- K6: bitonic sort (desc) + box transform ----------------
__global__ void k_sortbox(const float* __restrict__ bbox,
                          const float* __restrict__ anchors) {
    extern __shared__ unsigned long long sk[];   // 8192 keys = 64 KB
    int b = blockIdx.x;
    int cnt = g_candcnt[b];
    if (cnt > CAP) cnt = CAP;
    for (int i = threadIdx.x; i < CAP; i += blockDim.x)
        sk[i] = (i < cnt) ? g_cand[b * CAP + i] : 0ULL;
    __syncthreads();

    for (int k = 2; k <= CAP; k <<= 1) {
        for (int j = k >> 1; j > 0; j >>= 1) {
            for (int i = threadIdx.x; i < CAP; i += blockDim.x) {
                int l = i ^ j;
                if (l > i) {
                    unsigned long long a = sk[i], c = sk[l];
                    bool seg = ((i & k) == 0);   // descending sort
                    if (seg ? (a < c) : (a > c)) { sk[i] = c; sk[l] = a; }
                }
            }
            __syncthreads();
        }
    }

    for (int t = threadIdx.x; t < PRE; t += blockDim.x) {
        unsigned long long key = sk[t];
        unsigned u = (unsigned)(key >> 32);
        unsigned idx = ~((unsigned)key);
        float o0 = 0.f, o1 = 0.f, o2 = 0.f, o3 = 0.f, score = -1.f;
        if (key != 0ULL && idx < (unsigned)NVAL) {
            score = unflip_f(u);
            int base = (b * NVAL + (int)idx) * 4;
            float ay1 = anchors[base + 0];
            float ax1 = anchors[base + 1];
            float ay2 = anchors[base + 2];
            float ax2 = anchors[base + 3];
            float d0 = bbox[base + 0] * 0.1f;
            float d1 = bbox[base + 1] * 0.1f;
            float d2 = bbox[base + 2] * 0.2f;
            float d3 = bbox[base + 3] * 0.2f;
            float h = ay2 - ay1;
            float w = ax2 - ax1;
            float cy = ay1 + 0.5f * h;
            float cx = ax1 + 0.5f * w;
            cy = cy + d0 * h;
            cx = cx + d1 * w;
            h = h * expf(d2);
            w = w * expf(d3);
            float y1 = cy - 0.5f * h;
            float x1 = cx - 0.5f * w;
            float y2 = y1 + h;
            float x2 = x1 + w;
            o0 = fminf(fmaxf(y1, 0.f), 1.f);
            o1 = fminf(fmaxf(x1, 0.f), 1.f);
            o2 = fminf(fmaxf(y2, 0.f), 1.f);
            o3 = fminf(fmaxf(x2, 0.f), 1.f);
        }
        int ob = (b * PRE + t) * 4;
        g_boxes[ob + 0] = o0;
        g_boxes[ob + 1] = o1;
        g_boxes[ob + 2] = o2;
        g_boxes[ob + 3] = o3;
        g_scores[b * PRE + t] = score;
    }
}

// ---------------- K7: greedy NMS, one block per batch ----------------
__global__ void k_nms(float* __restrict__ out) {
    extern __shared__ char sm[];
    float* y1 = (float*)sm;
    float* x1 = y1 + PRE;
    float* y2 = x1 + PRE;
    float* x2 = y2 + PRE;
    float* area = x2 + PRE;
    unsigned* mask = (unsigned*)(area + PRE);
    __shared__ int s_pick;
    __shared__ int s_cur;
    __shared__ float s_box[4];

    int b = blockIdx.x;
    int tid = threadIdx.x;

    for (int t = tid; t < PROP * 4; t += blockDim.x) out[b * PROP * 4 + t] = 0.f;
    for (int w = tid; w < NW; w += blockDim.x) mask[w] = 0u;
    __syncthreads();
    for (int j = tid; j < PRE; j += blockDim.x) {
        int base = (b * PRE + j) * 4;
        float a0 = g_boxes[base + 0];
        float a1 = g_boxes[base + 1];
        float a2 = g_boxes[base + 2];
        float a3 = g_boxes[base + 3];
        y1[j] = a0; x1[j] = a1; y2[j] = a2; x2[j] = a3;
        area[j] = (a2 - a0) * (a3 - a1);
        if (g_scores[b * PRE + j] >= 0.5f)
            atomicOr(&mask[j >> 5], 1u << (j & 31));
    }
    if (tid == 0) s_cur = 0;
    __syncthreads();

    for (int p = 0; p < PROP; ++p) {
        if (tid == 0) {
            int i = -1;
            int w = s_cur >> 5;
            while (w < NW) {
                unsigned m = mask[w];
                if (m) { i = w * 32 + __ffs(m) - 1; break; }
                ++w;
            }
            if (i >= 0) {
                mask[i >> 5] &= ~(1u << (i & 31));   // self-suppress (matches ref)
                s_cur = i;
                s_box[0] = y1[i]; s_box[1] = x1[i];
                s_box[2] = y2[i]; s_box[3] = x2[i];
            }
            s_pick = i;
        }
        __syncthreads();
        int i = s_pick;
        if (i < 0) break;
        if (tid < 4) out[(b * PROP + p) * 4 + tid] = s_box[tid];
        float by1 = s_box[0], bx1 = s_box[1], by2 = s_box[2], bx2 = s_box[3];
        float ba = (by2 - by1) * (bx2 - bx1);
        for (int j = i + 1 + tid; j < PRE; j += blockDim.x) {
            if (mask[j >> 5] & (1u << (j & 31))) {
                float yy1 = fmaxf(by1, y1[j]);
                float xx1 = fmaxf(bx1, x1[j]);
                float yy2 = fminf(by2, y2[j]);
                float xx2 = fminf(bx2, x2[j]);
                float inter = fmaxf(yy2 - yy1, 0.f) * fmaxf(xx2 - xx1, 0.f);
                float iou = inter / (ba + area[j] - inter + 1e-8f);
                if (iou >= 0.7f)
                    atomicAnd(&mask[j >> 5], ~(1u << (j & 31)));
            }
        }
        __syncthreads();
    }
}

// ---------------- launch ----------------
extern "C" void kernel_launch(void* const* d_in, const int* in_sizes, int n_in,
                              void* d_out, int out_size) {
    const float* probs   = (const float*)d_in[0];
    const float* bbox    = (const float*)d_in[1];
    const float* anchors = (const float*)d_in[2];
    float* out = (float*)d_out;

    static bool attr_done = false;
    // cudaFuncSetAttribute is idempotent host-side config (not device alloc,
    // not a stream op); safe under capture. Call every time for determinism.
    cudaFuncSetAttribute(k_sortbox, cudaFuncAttributeMaxDynamicSharedMemorySize,
                         CAP * (int)sizeof(unsigned long long));
    size_t nms_smem = (size_t)PRE * 5 * sizeof(float) + NW * sizeof(unsigned);
    cudaFuncSetAttribute(k_nms, cudaFuncAttributeMaxDynamicSharedMemorySize,
                         (int)nms_smem);
    (void)attr_done;
    (void)in_sizes; (void)n_in; (void)out_size;

    k_zero<<<512, 256>>>();

    dim3 gridN(256, BATCH);
    k_score_hist<<<gridN, 256>>>(probs);
    k_findbin1<<<BATCH, 256>>>();
    k_hist2<<<gridN, 256>>>();
    k_findbin2<<<BATCH, 256>>>();
    k_compact<<<gridN, 256>>>();
    k_sortbox<<<BATCH, 1024, CAP * sizeof(unsigned long long)>>>(bbox, anchors);
    k_nms<<<BATCH, 512, nms_smem>>>(out);
}

// round 3
// speedup vs baseline: 3.7522x; 3.7522x over previous
#include <cuda_runtime.h>
#include <cstdint>

#define BATCH 8
#define NVAL  261888
#define PRE   6000
#define CAP   8192
#define NWORD 188          // ceil(6000/32)
#define WROW  192          // padded row words
#define PROP  1000

// ---------------- scratch (static device globals; no allocation) ----------------
__device__ unsigned           g_u[BATCH * NVAL];
__device__ unsigned           g_hist1[BATCH * 65536];
__device__ unsigned           g_hist2[BATCH * 65536];
__device__ unsigned           g_b1[BATCH];
__device__ unsigned           g_above1[BATCH];
__device__ unsigned           g_thresh[BATCH];
__device__ int                g_candcnt[BATCH];
__device__ unsigned long long g_cand[BATCH * CAP];
__device__ float              g_boxes[BATCH * PRE * 4];
__device__ unsigned           g_alive[BATCH * WROW];
__device__ unsigned           g_mat[(size_t)BATCH * PRE * WROW];   // ~36.9 MB

__device__ __forceinline__ unsigned flip_f(float f) {
    unsigned b = __float_as_uint(f);
    unsigned mask = (unsigned)((int)b >> 31) | 0x80000000u;
    return b ^ mask;
}
__device__ __forceinline__ float unflip_f(unsigned u) {
    unsigned mask = (u >> 31) ? 0x80000000u : 0xFFFFFFFFu;
    return __uint_as_float(u ^ mask);
}

// ---------------- K0: zero scratch ----------------
__global__ void k_zero() {
    int total = BATCH * 65536;
    for (int i = blockIdx.x * blockDim.x + threadIdx.x; i < total;
         i += gridDim.x * blockDim.x) {
        g_hist1[i] = 0;
        g_hist2[i] = 0;
    }
    int gid = blockIdx.x * blockDim.x + threadIdx.x;
    if (gid < BATCH) g_candcnt[gid] = 0;
    if (gid < BATCH * WROW) g_alive[gid] = 0u;
}

// ---------------- K1: flip scores, hist of high 16 bits ----------------
__global__ void k_score_hist(const float* __restrict__ probs) {
    int b = blockIdx.y;
    const float2* p2 = (const float2*)probs;
    for (int n = blockIdx.x * blockDim.x + threadIdx.x; n < NVAL;
         n += gridDim.x * blockDim.x) {
        float s = p2[b * NVAL + n].y;
        unsigned u = flip_f(s);
        g_u[b * NVAL + n] = u;
        atomicAdd(&g_hist1[b * 65536 + (u >> 16)], 1u);
    }
}

// ---------------- K2: find high-16 bin containing rank PRE ----------------
__global__ void k_findbin1() {
    __shared__ unsigned part[256];
    int b = blockIdx.x;
    const unsigned* hist = g_hist1 + b * 65536;
    unsigned s = 0;
    int base = threadIdx.x * 256;
    for (int i = 0; i < 256; ++i) s += hist[base + i];
    part[threadIdx.x] = s;
    __syncthreads();
    if (threadIdx.x == 0) {
        unsigned acc = 0;
        for (int t = 255; t >= 0; --t) {
            if (acc + part[t] >= (unsigned)PRE) {
                for (int bin = t * 256 + 255; bin >= t * 256; --bin) {
                    unsigned h = hist[bin];
                    if (acc + h >= (unsigned)PRE) {
                        g_b1[b] = (unsigned)bin;
                        g_above1[b] = acc;
                        return;
                    }
                    acc += h;
                }
            }
            acc += part[t];
        }
        g_b1[b] = 0; g_above1[b] = 0;
    }
}

// ---------------- K3: hist of low 16 bits within bin b1 ----------------
__global__ void k_hist2() {
    int b = blockIdx.y;
    unsigned b1 = g_b1[b];
    for (int n = blockIdx.x * blockDim.x + threadIdx.x; n < NVAL;
         n += gridDim.x * blockDim.x) {
        unsigned u = g_u[b * NVAL + n];
        if ((u >> 16) == b1)
            atomicAdd(&g_hist2[b * 65536 + (u & 0xFFFFu)], 1u);
    }
}

// ---------------- K4: exact 32-bit threshold ----------------
__global__ void k_findbin2() {
    __shared__ unsigned part[256];
    int b = blockIdx.x;
    const unsigned* hist = g_hist2 + b * 65536;
    unsigned K = (unsigned)PRE - g_above1[b];
    unsigned s = 0;
    int base = threadIdx.x * 256;
    for (int i = 0; i < 256; ++i) s += hist[base + i];
    part[threadIdx.x] = s;
    __syncthreads();
    if (threadIdx.x == 0) {
        unsigned acc = 0;
        unsigned b2 = 0;
        for (int t = 255; t >= 0; --t) {
            if (acc + part[t] >= K) {
                for (int bin = t * 256 + 255; bin >= t * 256; --bin) {
                    unsigned h = hist[bin];
                    if (acc + h >= K) { b2 = (unsigned)bin; goto done; }
                    acc += h;
                }
            }
            acc += part[t];
        }
done:
        g_thresh[b] = (g_b1[b] << 16) | b2;
    }
}

// ---------------- K5: compact candidates (u >= T) ----------------
__global__ void k_compact() {
    int b = blockIdx.y;
    unsigned T = g_thresh[b];
    for (int n = blockIdx.x * blockDim.x + threadIdx.x; n < NVAL;
         n += gridDim.x * blockDim.x) {
        unsigned u = g_u[b * NVAL + n];
        if (u >= T) {
            int pos = atomicAdd(&g_candcnt[b], 1);
            if (pos < CAP)
                g_cand[b * CAP + pos] =
                    ((unsigned long long)u << 32) | (unsigned)(~(unsigned)n);
        }
    }
}

// ---------------- K6: bitonic sort (desc) + box transform + alive bits ----------------
__global__ void k_sortbox(const float* __restrict__ bbox,
                          const float* __restrict__ anchors) {
    extern __shared__ unsigned long long sk[];   // 8192 keys = 64 KB
    int b = blockIdx.x;
    int cnt = g_candcnt[b];
    if (cnt > CAP) cnt = CAP;
    for (int i = threadIdx.x; i < CAP; i += blockDim.x)
        sk[i] = (i < cnt) ? g_cand[b * CAP + i] : 0ULL;
    __syncthreads();

    for (int k = 2; k <= CAP; k <<= 1) {
        for (int j = k >> 1; j > 0; j >>= 1) {
            for (int i = threadIdx.x; i < CAP; i += blockDim.x) {
                int l = i ^ j;
                if (l > i) {
                    unsigned long long a = sk[i], c = sk[l];
                    bool seg = ((i & k) == 0);   // descending
                    if (seg ? (a < c) : (a > c)) { sk[i] = c; sk[l] = a; }
                }
            }
            __syncthreads();
        }
    }

    for (int t = threadIdx.x; t < PRE; t += blockDim.x) {
        unsigned long long key = sk[t];
        unsigned u = (unsigned)(key >> 32);
        unsigned idx = ~((unsigned)key);
        float o0 = 0.f, o1 = 0.f, o2 = 0.f, o3 = 0.f;
        bool live = false;
        if (key != 0ULL && idx < (unsigned)NVAL) {
            float score = unflip_f(u);
            live = (score >= 0.5f);
            int base = (b * NVAL + (int)idx) * 4;
            float ay1 = anchors[base + 0];
            float ax1 = anchors[base + 1];
            float ay2 = anchors[base + 2];
            float ax2 = anchors[base + 3];
            float d0 = bbox[base + 0] * 0.1f;
            float d1 = bbox[base + 1] * 0.1f;
            float d2 = bbox[base + 2] * 0.2f;
            float d3 = bbox[base + 3] * 0.2f;
            float h = ay2 - ay1;
            float w = ax2 - ax1;
            float cy = ay1 + 0.5f * h;
            float cx = ax1 + 0.5f * w;
            cy = cy + d0 * h;
            cx = cx + d1 * w;
            h = h * expf(d2);
            w = w * expf(d3);
            float y1 = cy - 0.5f * h;
            float x1 = cx - 0.5f * w;
            float y2 = y1 + h;
            float x2 = x1 + w;
            o0 = fminf(fmaxf(y1, 0.f), 1.f);
            o1 = fminf(fmaxf(x1, 0.f), 1.f);
            o2 = fminf(fmaxf(y2, 0.f), 1.f);
            o3 = fminf(fmaxf(x2, 0.f), 1.f);
        }
        int ob = (b * PRE + t) * 4;
        g_boxes[ob + 0] = o0;
        g_boxes[ob + 1] = o1;
        g_boxes[ob + 2] = o2;
        g_boxes[ob + 3] = o3;
        if (live) atomicOr(&g_alive[b * WROW + (t >> 5)], 1u << (t & 31));
    }
}

// ---------------- K7: suppression matrix build ----------------
// Block (64 threads): rows by*64.. vs cols bx*64.., only bx >= by.
__global__ void k_build() {
    int bx = blockIdx.x, by = blockIdx.y, b = blockIdx.z;
    if (bx < by) return;
    __shared__ float cy1[64], cx1[64], cy2[64], cx2[64], ca[64];
    int t = threadIdx.x;
    int j0 = bx * 64;
    int jn = PRE - j0; if (jn > 64) jn = 64;
    if (t < jn) {
        int base = (b * PRE + j0 + t) * 4;
        float a0 = g_boxes[base + 0];
        float a1 = g_boxes[base + 1];
        float a2 = g_boxes[base + 2];
        float a3 = g_boxes[base + 3];
        cy1[t] = a0; cx1[t] = a1; cy2[t] = a2; cx2[t] = a3;
        ca[t] = (a2 - a0) * (a3 - a1);
    }
    __syncthreads();
    int i = by * 64 + t;
    if (i >= PRE) return;
    int base = (b * PRE + i) * 4;
    float ry1 = g_boxes[base + 0];
    float rx1 = g_boxes[base + 1];
    float ry2 = g_boxes[base + 2];
    float rx2 = g_boxes[base + 3];
    float ra = (ry2 - ry1) * (rx2 - rx1);
    unsigned w0 = 0, w1 = 0;
    #pragma unroll 8
    for (int jj = 0; jj < jn; ++jj) {
        int j = j0 + jj;
        bool sup = false;
        if (j > i) {
            float yy1 = fmaxf(ry1, cy1[jj]);
            float xx1 = fmaxf(rx1, cx1[jj]);
            float yy2 = fminf(ry2, cy2[jj]);
            float xx2 = fminf(rx2, cx2[jj]);
            float inter = fmaxf(yy2 - yy1, 0.f) * fmaxf(xx2 - xx1, 0.f);
            float u = ((ra + ca[jj]) - inter) + 1e-8f;
            // guard-banded multiply compare; exact IEEE div only near boundary
            if (inter >= 0.700007f * u)       sup = true;
            else if (inter <= 0.699993f * u)  sup = false;
            else                              sup = (inter / u >= 0.7f);
        }
        if (jj < 32) w0 |= ((unsigned)sup) << jj;
        else         w1 |= ((unsigned)sup) << (jj - 32);
    }
    size_t rb = ((size_t)b * PRE + i) * WROW + bx * 2;
    g_mat[rb + 0] = w0;
    g_mat[rb + 1] = w1;
}

// ---------------- K8: warp-serial NMS pass (one warp per batch) ----------------
__global__ void k_nms_serial(float* __restrict__ out) {
    int b = blockIdx.x;
    int lane = threadIdx.x;

    // zero output
    for (int t = lane; t < PROP * 4; t += 32) out[b * PROP * 4 + t] = 0.f;

    // alive mask in registers: lane owns words lane, lane+32, ..., lane+160
    unsigned alive[6];
    #pragma unroll
    for (int k = 0; k < 6; ++k)
        alive[k] = g_alive[b * WROW + k * 32 + lane];

    const unsigned* mat = g_mat + (size_t)b * PRE * WROW;

    for (int p = 0; p < PROP; ++p) {
        // find global first set bit
        unsigned best = 0xFFFFFFFFu;
        #pragma unroll
        for (int k = 0; k < 6; ++k) {
            if (best == 0xFFFFFFFFu && alive[k])
                best = (unsigned)((k * 32 + lane) * 32) + (__ffs(alive[k]) - 1);
        }
        #pragma unroll
        for (int off = 16; off; off >>= 1) {
            unsigned o = __shfl_xor_sync(0xFFFFFFFFu, best, off);
            best = best < o ? best : o;
        }
        if (best == 0xFFFFFFFFu) break;
        int i = (int)best;

        // self-clear
        int w = i >> 5;
        if (lane == (w & 31)) alive[w >> 5] &= ~(1u << (i & 31));

        // emit box
        if (lane < 4) out[(b * PROP + p) * 4 + lane] = g_boxes[(b * PRE + i) * 4 + lane];

        // suppress: AND out row i
        const unsigned* row = mat + (size_t)i * WROW;
        #pragma unroll
        for (int k = 0; k < 6; ++k)
            alive[k] &= ~row[k * 32 + lane];
    }
}

// ---------------- launch ----------------
extern "C" void kernel_launch(void* const* d_in, const int* in_sizes, int n_in,
                              void* d_out, int out_size) {
    const float* probs   = (const float*)d_in[0];
    const float* bbox    = (const float*)d_in[1];
    const float* anchors = (const float*)d_in[2];
    float* out = (float*)d_out;
    (void)in_sizes; (void)n_in; (void)out_size;

    cudaFuncSetAttribute(k_sortbox, cudaFuncAttributeMaxDynamicSharedMemorySize,
                         CAP * (int)sizeof(unsigned long long));

    k_zero<<<512, 256>>>();

    dim3 gridN(256, BATCH);
    k_score_hist<<<gridN, 256>>>(probs);
    k_findbin1<<<BATCH, 256>>>();
    k_hist2<<<gridN, 256>>>();
    k_findbin2<<<BATCH, 256>>>();
    k_compact<<<gridN, 256>>>();
    k_sortbox<<<BATCH, 1024, CAP * sizeof(unsigned long long)>>>(bbox, anchors);

    dim3 gridB((PRE + 63) / 64, (PRE + 63) / 64, BATCH);
    k_build<<<gridB, 64>>>();

    k_nms_serial<<<BATCH, 32>>>(out);
}

// round 4
// speedup vs baseline: 5.6435x; 1.5040x over previous
#include <cuda_runtime.h>
#include <cstdint>

#define BATCH 8
#define NVAL  261888
#define PRE   6000
#define CAP   8192
#define WROW  192          // padded row words (188 used)
#define PROP  1000
#define SPEC  8            // speculative picks per round
#define FULLM 0xFFFFFFFFu

// ---------------- scratch (static device globals; no allocation) ----------------
__device__ unsigned           g_u[BATCH * NVAL];
__device__ unsigned           g_hist1[BATCH * 65536];
__device__ unsigned           g_hist2[BATCH * 65536];
__device__ unsigned           g_b1[BATCH];
__device__ unsigned           g_above1[BATCH];
__device__ unsigned           g_thresh[BATCH];
__device__ int                g_candcnt[BATCH];
__device__ unsigned long long g_cand[BATCH * CAP];
__device__ float              g_boxes[BATCH * PRE * 4];
__device__ unsigned           g_alive[BATCH * WROW];
__device__ unsigned           g_mat[(size_t)BATCH * PRE * WROW];   // ~36.9 MB

__device__ __forceinline__ unsigned flip_f(float f) {
    unsigned b = __float_as_uint(f);
    unsigned mask = (unsigned)((int)b >> 31) | 0x80000000u;
    return b ^ mask;
}
__device__ __forceinline__ float unflip_f(unsigned u) {
    unsigned mask = (u >> 31) ? 0x80000000u : 0xFFFFFFFFu;
    return __uint_as_float(u ^ mask);
}

// ---------------- K0: zero scratch ----------------
__global__ void k_zero() {
    int total = BATCH * 65536;
    for (int i = blockIdx.x * blockDim.x + threadIdx.x; i < total;
         i += gridDim.x * blockDim.x) {
        g_hist1[i] = 0;
        g_hist2[i] = 0;
    }
    int gid = blockIdx.x * blockDim.x + threadIdx.x;
    if (gid < BATCH) g_candcnt[gid] = 0;
    if (gid < BATCH * WROW) g_alive[gid] = 0u;
}

// ---------------- K1: flip scores, hist of high 16 bits ----------------
__global__ void k_score_hist(const float* __restrict__ probs) {
    int b = blockIdx.y;
    const float2* p2 = (const float2*)probs;
    for (int n = blockIdx.x * blockDim.x + threadIdx.x; n < NVAL;
         n += gridDim.x * blockDim.x) {
        float s = p2[b * NVAL + n].y;
        unsigned u = flip_f(s);
        g_u[b * NVAL + n] = u;
        atomicAdd(&g_hist1[b * 65536 + (u >> 16)], 1u);
    }
}

// ---------------- K2: find high-16 bin containing rank PRE ----------------
__global__ void k_findbin1() {
    __shared__ unsigned part[256];
    int b = blockIdx.x;
    const unsigned* hist = g_hist1 + b * 65536;
    unsigned s = 0;
    int base = threadIdx.x * 256;
    for (int i = 0; i < 256; ++i) s += hist[base + i];
    part[threadIdx.x] = s;
    __syncthreads();
    if (threadIdx.x == 0) {
        unsigned acc = 0;
        for (int t = 255; t >= 0; --t) {
            if (acc + part[t] >= (unsigned)PRE) {
                for (int bin = t * 256 + 255; bin >= t * 256; --bin) {
                    unsigned h = hist[bin];
                    if (acc + h >= (unsigned)PRE) {
                        g_b1[b] = (unsigned)bin;
                        g_above1[b] = acc;
                        return;
                    }
                    acc += h;
                }
            }
            acc += part[t];
        }
        g_b1[b] = 0; g_above1[b] = 0;
    }
}

// ---------------- K3: hist of low 16 bits within bin b1 ----------------
__global__ void k_hist2() {
    int b = blockIdx.y;
    unsigned b1 = g_b1[b];
    for (int n = blockIdx.x * blockDim.x + threadIdx.x; n < NVAL;
         n += gridDim.x * blockDim.x) {
        unsigned u = g_u[b * NVAL + n];
        if ((u >> 16) == b1)
            atomicAdd(&g_hist2[b * 65536 + (u & 0xFFFFu)], 1u);
    }
}

// ---------------- K4: exact 32-bit threshold ----------------
__global__ void k_findbin2() {
    __shared__ unsigned part[256];
    int b = blockIdx.x;
    const unsigned* hist = g_hist2 + b * 65536;
    unsigned K = (unsigned)PRE - g_above1[b];
    unsigned s = 0;
    int base = threadIdx.x * 256;
    for (int i = 0; i < 256; ++i) s += hist[base + i];
    part[threadIdx.x] = s;
    __syncthreads();
    if (threadIdx.x == 0) {
        unsigned acc = 0;
        unsigned b2 = 0;
        for (int t = 255; t >= 0; --t) {
            if (acc + part[t] >= K) {
                for (int bin = t * 256 + 255; bin >= t * 256; --bin) {
                    unsigned h = hist[bin];
                    if (acc + h >= K) { b2 = (unsigned)bin; goto done; }
                    acc += h;
                }
            }
            acc += part[t];
        }
done:
        g_thresh[b] = (g_b1[b] << 16) | b2;
    }
}

// ---------------- K5: compact candidates (u >= T) ----------------
__global__ void k_compact() {
    int b = blockIdx.y;
    unsigned T = g_thresh[b];
    for (int n = blockIdx.x * blockDim.x + threadIdx.x; n < NVAL;
         n += gridDim.x * blockDim.x) {
        unsigned u = g_u[b * NVAL + n];
        if (u >= T) {
            int pos = atomicAdd(&g_candcnt[b], 1);
            if (pos < CAP)
                g_cand[b * CAP + pos] =
                    ((unsigned long long)u << 32) | (unsigned)(~(unsigned)n);
        }
    }
}

// ---------------- K6: bitonic sort (desc) + box transform + alive bits ----------------
__global__ void k_sortbox(const float* __restrict__ bbox,
                          const float* __restrict__ anchors) {
    extern __shared__ unsigned long long sk[];   // 8192 keys = 64 KB
    int b = blockIdx.x;
    int cnt = g_candcnt[b];
    if (cnt > CAP) cnt = CAP;
    for (int i = threadIdx.x; i < CAP; i += blockDim.x)
        sk[i] = (i < cnt) ? g_cand[b * CAP + i] : 0ULL;
    __syncthreads();

    for (int k = 2; k <= CAP; k <<= 1) {
        for (int j = k >> 1; j > 0; j >>= 1) {
            for (int i = threadIdx.x; i < CAP; i += blockDim.x) {
                int l = i ^ j;
                if (l > i) {
                    unsigned long long a = sk[i], c = sk[l];
                    bool seg = ((i & k) == 0);   // descending
                    if (seg ? (a < c) : (a > c)) { sk[i] = c; sk[l] = a; }
                }
            }
            __syncthreads();
        }
    }

    for (int t = threadIdx.x; t < PRE; t += blockDim.x) {
        unsigned long long key = sk[t];
        unsigned u = (unsigned)(key >> 32);
        unsigned idx = ~((unsigned)key);
        float o0 = 0.f, o1 = 0.f, o2 = 0.f, o3 = 0.f;
        bool live = false;
        if (key != 0ULL && idx < (unsigned)NVAL) {
            float score = unflip_f(u);
            live = (score >= 0.5f);
            int base = (b * NVAL + (int)idx) * 4;
            float ay1 = anchors[base + 0];
            float ax1 = anchors[base + 1];
            float ay2 = anchors[base + 2];
            float ax2 = anchors[base + 3];
            float d0 = bbox[base + 0] * 0.1f;
            float d1 = bbox[base + 1] * 0.1f;
            float d2 = bbox[base + 2] * 0.2f;
            float d3 = bbox[base + 3] * 0.2f;
            float h = ay2 - ay1;
            float w = ax2 - ax1;
            float cy = ay1 + 0.5f * h;
            float cx = ax1 + 0.5f * w;
            cy = cy + d0 * h;
            cx = cx + d1 * w;
            h = h * expf(d2);
            w = w * expf(d3);
            float y1 = cy - 0.5f * h;
            float x1 = cx - 0.5f * w;
            float y2 = y1 + h;
            float x2 = x1 + w;
            o0 = fminf(fmaxf(y1, 0.f), 1.f);
            o1 = fminf(fmaxf(x1, 0.f), 1.f);
            o2 = fminf(fmaxf(y2, 0.f), 1.f);
            o3 = fminf(fmaxf(x2, 0.f), 1.f);
        }
        int ob = (b * PRE + t) * 4;
        g_boxes[ob + 0] = o0;
        g_boxes[ob + 1] = o1;
        g_boxes[ob + 2] = o2;
        g_boxes[ob + 3] = o3;
        if (live) atomicOr(&g_alive[b * WROW + (t >> 5)], 1u << (t & 31));
    }
}

// ---------------- K7: suppression matrix build ----------------
// Block (128 threads): rows [by*128, +128) vs cols [bx*64, +64).
__global__ void k_build() {
    int bx = blockIdx.x, by = blockIdx.y, b = blockIdx.z;
    // all pairs in this tile have j < i  -> garbage words are never-alive bits
    if (bx * 64 + 64 <= by * 128) return;
    __shared__ float4 cb[64];
    __shared__ float  ca[64];
    int t = threadIdx.x;
    int j0 = bx * 64;
    int jn = PRE - j0; if (jn > 64) jn = 64;
    const float4* boxes4 = (const float4*)g_boxes;
    if (t < jn) {
        float4 a = boxes4[b * PRE + j0 + t];
        cb[t] = a;
        ca[t] = (a.z - a.x) * (a.w - a.y);
    }
    __syncthreads();
    int i = by * 128 + t;
    if (i >= PRE) return;
    float4 r = boxes4[b * PRE + i];
    float ra = (r.z - r.x) * (r.w - r.y);
    unsigned w0 = 0, w1 = 0;
    #pragma unroll 8
    for (int jj = 0; jj < jn; ++jj) {
        int j = j0 + jj;
        bool sup = false;
        if (j > i) {
            float4 c = cb[jj];
            float yy1 = fmaxf(r.x, c.x);
            float xx1 = fmaxf(r.y, c.y);
            float yy2 = fminf(r.z, c.z);
            float xx2 = fminf(r.w, c.w);
            float inter = fmaxf(yy2 - yy1, 0.f) * fmaxf(xx2 - xx1, 0.f);
            float u = ((ra + ca[jj]) - inter) + 1e-8f;
            if (inter >= 0.700007f * u)       sup = true;
            else if (inter <= 0.699993f * u)  sup = false;
            else                              sup = (inter / u >= 0.7f);
        }
        if (jj < 32) w0 |= ((unsigned)sup) << jj;
        else         w1 |= ((unsigned)sup) << (jj - 32);
    }
    uint2* rb = (uint2*)(g_mat + ((size_t)b * PRE + i) * WROW + bx * 2);
    *rb = make_uint2(w0, w1);
}

// ---------------- K8: speculative warp-serial NMS (one warp per batch) ----------------
__global__ void k_nms_multi(float* __restrict__ out) {
    __shared__ int cand_s[SPEC];
    int b = blockIdx.x;
    int lane = threadIdx.x;

    for (int t = lane; t < PROP * 4; t += 32) out[b * PROP * 4 + t] = 0.f;

    // alive mask in registers: lane owns words k*32+lane, k=0..5
    unsigned alive[6];
    #pragma unroll
    for (int k = 0; k < 6; ++k)
        alive[k] = g_alive[b * WROW + k * 32 + lane];

    const unsigned* mat = g_mat + (size_t)b * PRE * WROW;

    int p = 0;
    while (p < PROP) {
        // ballots: which lanes hold any alive bit per reg slot
        unsigned bal[6];
        #pragma unroll
        for (int k = 0; k < 6; ++k)
            bal[k] = __ballot_sync(FULLM, alive[k] != 0u);

        // extract the SPEC smallest alive bit positions (uniform across warp)
        int found = 0;
        #pragma unroll
        for (int k = 0; k < 6; ++k) {
            unsigned bb = bal[k];
            while (bb && found < SPEC) {
                int ln = __ffs(bb) - 1;
                unsigned w = __shfl_sync(FULLM, alive[k], ln);
                int base = (k * 32 + ln) * 32;
                while (w && found < SPEC) {
                    cand_s[found++] = base + (__ffs(w) - 1);
                    w &= w - 1;
                }
                bb &= bb - 1;
            }
            if (found >= SPEC) break;
        }
        if (found == 0) break;

        // batch-load all candidate rows (one L2 round trip)
        unsigned rw[SPEC][6];
        int cidx[SPEC];
        #pragma unroll
        for (int c = 0; c < SPEC; ++c) {
            cidx[c] = (c < found) ? cand_s[c] : -1;
            if (cidx[c] >= 0) {
                const unsigned* row = mat + (size_t)cidx[c] * WROW;
                #pragma unroll
                for (int k = 0; k < 6; ++k) rw[c][k] = row[k * 32 + lane];
            }
        }

        // sequential validate + accept (pure ALU/shfl)
        #pragma unroll
        for (int c = 0; c < SPEC; ++c) {
            if (cidx[c] < 0 || p >= PROP) continue;
            int i = cidx[c];
            int wk = i >> 10;            // register slot
            int owner = (i >> 5) & 31;   // owning lane
            unsigned word = __shfl_sync(FULLM, alive[wk], owner);
            if (!((word >> (i & 31)) & 1u)) continue;   // suppressed this round
            // accept
            if (lane == owner) alive[wk] &= ~(1u << (i & 31));
            if (lane < 4)
                out[(b * PROP + p) * 4 + lane] = g_boxes[(b * PRE + i) * 4 + lane];
            #pragma unroll
            for (int k = 0; k < 6; ++k) alive[k] &= ~rw[c][k];
            ++p;
        }
    }
}

// ---------------- launch ----------------
extern "C" void kernel_launch(void* const* d_in, const int* in_sizes, int n_in,
                              void* d_out, int out_size) {
    const float* probs   = (const float*)d_in[0];
    const float* bbox    = (const float*)d_in[1];
    const float* anchors = (const float*)d_in[2];
    float* out = (float*)d_out;
    (void)in_sizes; (void)n_in; (void)out_size;

    cudaFuncSetAttribute(k_sortbox, cudaFuncAttributeMaxDynamicSharedMemorySize,
                         CAP * (int)sizeof(unsigned long long));

    k_zero<<<512, 256>>>();

    dim3 gridN(256, BATCH);
    k_score_hist<<<gridN, 256>>>(probs);
    k_findbin1<<<BATCH, 256>>>();
    k_hist2<<<gridN, 256>>>();
    k_findbin2<<<BATCH, 256>>>();
    k_compact<<<gridN, 256>>>();
    k_sortbox<<<BATCH, 1024, CAP * sizeof(unsigned long long)>>>(bbox, anchors);

    dim3 gridB((PRE + 63) / 64, (PRE + 127) / 128, BATCH);
    k_build<<<gridB, 128>>>();

    k_nms_multi<<<BATCH, 32>>>(out);
}

// round 5
// speedup vs baseline: 6.8103x; 1.2068x over previous
#include <cuda_runtime.h>
#include <cstdint>

#define BATCH 8
#define NVAL  261888
#define PRE   6000
#define CAP   8192
#define WROW  192          // alive words allocated per batch (188 used)
#define PROP  1000
#define W     2048         // NMS fast-path window (candidates)
#define MWORDS 64          // matrix row words (W/32)
#define SPEC  8            // speculative picks per round
#define FULLM 0xFFFFFFFFu

// ---------------- scratch (static device globals; no allocation) ----------------
__device__ unsigned           g_u[BATCH * NVAL];
__device__ unsigned           g_hist1[BATCH * 65536];
__device__ unsigned           g_hist2[BATCH * 65536];
__device__ unsigned           g_b1[BATCH];
__device__ unsigned           g_above1[BATCH];
__device__ unsigned           g_thresh[BATCH];
__device__ int                g_candcnt[BATCH];
__device__ unsigned long long g_cand[BATCH * CAP];
__device__ float              g_boxes[BATCH * PRE * 4];
__device__ unsigned           g_alive[BATCH * WROW];
__device__ unsigned           g_mat[(size_t)BATCH * W * MWORDS];   // 4 MB

__device__ __forceinline__ unsigned flip_f(float f) {
    unsigned b = __float_as_uint(f);
    unsigned mask = (unsigned)((int)b >> 31) | 0x80000000u;
    return b ^ mask;
}
__device__ __forceinline__ float unflip_f(unsigned u) {
    unsigned mask = (u >> 31) ? 0x80000000u : 0xFFFFFFFFu;
    return __uint_as_float(u ^ mask);
}

// exact reference-order IoU >= 0.7 test (slow path)
__device__ __forceinline__ bool iou_ge07(float4 a, float fa, float4 c) {
    float yy1 = fmaxf(a.x, c.x);
    float xx1 = fmaxf(a.y, c.y);
    float yy2 = fminf(a.z, c.z);
    float xx2 = fminf(a.w, c.w);
    float inter = fmaxf(yy2 - yy1, 0.f) * fmaxf(xx2 - xx1, 0.f);
    float ca = (c.z - c.x) * (c.w - c.y);
    float u = ((fa + ca) - inter) + 1e-8f;
    return inter / u >= 0.7f;
}

// ---------------- K0: zero scratch ----------------
__global__ void k_zero() {
    int total = BATCH * 65536;
    for (int i = blockIdx.x * blockDim.x + threadIdx.x; i < total;
         i += gridDim.x * blockDim.x) {
        g_hist1[i] = 0;
        g_hist2[i] = 0;
    }
    int gid = blockIdx.x * blockDim.x + threadIdx.x;
    if (gid < BATCH) g_candcnt[gid] = 0;
    if (gid < BATCH * WROW) g_alive[gid] = 0u;
}

// ---------------- K1: flip scores, hist of high 16 bits ----------------
__global__ void k_score_hist(const float* __restrict__ probs) {
    int b = blockIdx.y;
    const float2* p2 = (const float2*)probs;
    for (int n = blockIdx.x * blockDim.x + threadIdx.x; n < NVAL;
         n += gridDim.x * blockDim.x) {
        float s = p2[b * NVAL + n].y;
        unsigned u = flip_f(s);
        g_u[b * NVAL + n] = u;
        atomicAdd(&g_hist1[b * 65536 + (u >> 16)], 1u);
    }
}

// ---------------- K2: find high-16 bin containing rank PRE ----------------
__global__ void k_findbin1() {
    __shared__ unsigned part[256];
    int b = blockIdx.x;
    const unsigned* hist = g_hist1 + b * 65536;
    unsigned s = 0;
    int base = threadIdx.x * 256;
    for (int i = 0; i < 256; ++i) s += hist[base + i];
    part[threadIdx.x] = s;
    __syncthreads();
    if (threadIdx.x == 0) {
        unsigned acc = 0;
        for (int t = 255; t >= 0; --t) {
            if (acc + part[t] >= (unsigned)PRE) {
                for (int bin = t * 256 + 255; bin >= t * 256; --bin) {
                    unsigned h = hist[bin];
                    if (acc + h >= (unsigned)PRE) {
                        g_b1[b] = (unsigned)bin;
                        g_above1[b] = acc;
                        return;
                    }
                    acc += h;
                }
            }
            acc += part[t];
        }
        g_b1[b] = 0; g_above1[b] = 0;
    }
}

// ---------------- K3: hist of low 16 bits within bin b1 ----------------
__global__ void k_hist2() {
    int b = blockIdx.y;
    unsigned b1 = g_b1[b];
    for (int n = blockIdx.x * blockDim.x + threadIdx.x; n < NVAL;
         n += gridDim.x * blockDim.x) {
        unsigned u = g_u[b * NVAL + n];
        if ((u >> 16) == b1)
            atomicAdd(&g_hist2[b * 65536 + (u & 0xFFFFu)], 1u);
    }
}

// ---------------- K4: exact 32-bit threshold ----------------
__global__ void k_findbin2() {
    __shared__ unsigned part[256];
    int b = blockIdx.x;
    const unsigned* hist = g_hist2 + b * 65536;
    unsigned K = (unsigned)PRE - g_above1[b];
    unsigned s = 0;
    int base = threadIdx.x * 256;
    for (int i = 0; i < 256; ++i) s += hist[base + i];
    part[threadIdx.x] = s;
    __syncthreads();
    if (threadIdx.x == 0) {
        unsigned acc = 0;
        unsigned b2 = 0;
        for (int t = 255; t >= 0; --t) {
            if (acc + part[t] >= K) {
                for (int bin = t * 256 + 255; bin >= t * 256; --bin) {
                    unsigned h = hist[bin];
                    if (acc + h >= K) { b2 = (unsigned)bin; goto done; }
                    acc += h;
                }
            }
            acc += part[t];
        }
done:
        g_thresh[b] = (g_b1[b] << 16) | b2;
    }
}

// ---------------- K5: compact candidates (u >= T) ----------------
__global__ void k_compact() {
    int b = blockIdx.y;
    unsigned T = g_thresh[b];
    for (int n = blockIdx.x * blockDim.x + threadIdx.x; n < NVAL;
         n += gridDim.x * blockDim.x) {
        unsigned u = g_u[b * NVAL + n];
        if (u >= T) {
            int pos = atomicAdd(&g_candcnt[b], 1);
            if (pos < CAP)
                g_cand[b * CAP + pos] =
                    ((unsigned long long)u << 32) | (unsigned)(~(unsigned)n);
        }
    }
}

// ---------------- K6: bitonic sort (desc) + box transform + alive bits ----------------
__global__ void k_sortbox(const float* __restrict__ bbox,
                          const float* __restrict__ anchors) {
    extern __shared__ unsigned long long sk[];   // 8192 keys = 64 KB
    int b = blockIdx.x;
    int cnt = g_candcnt[b];
    if (cnt > CAP) cnt = CAP;
    for (int i = threadIdx.x; i < CAP; i += blockDim.x)
        sk[i] = (i < cnt) ? g_cand[b * CAP + i] : 0ULL;
    __syncthreads();

    for (int k = 2; k <= CAP; k <<= 1) {
        for (int j = k >> 1; j > 0; j >>= 1) {
            for (int i = threadIdx.x; i < CAP; i += blockDim.x) {
                int l = i ^ j;
                if (l > i) {
                    unsigned long long a = sk[i], c = sk[l];
                    bool seg = ((i & k) == 0);   // descending
                    if (seg ? (a < c) : (a > c)) { sk[i] = c; sk[l] = a; }
                }
            }
            __syncthreads();
        }
    }

    for (int t = threadIdx.x; t < PRE; t += blockDim.x) {
        unsigned long long key = sk[t];
        unsigned u = (unsigned)(key >> 32);
        unsigned idx = ~((unsigned)key);
        float o0 = 0.f, o1 = 0.f, o2 = 0.f, o3 = 0.f;
        bool live = false;
        if (key != 0ULL && idx < (unsigned)NVAL) {
            float score = unflip_f(u);
            live = (score >= 0.5f);
            int base = (b * NVAL + (int)idx) * 4;
            float ay1 = anchors[base + 0];
            float ax1 = anchors[base + 1];
            float ay2 = anchors[base + 2];
            float ax2 = anchors[base + 3];
            float d0 = bbox[base + 0] * 0.1f;
            float d1 = bbox[base + 1] * 0.1f;
            float d2 = bbox[base + 2] * 0.2f;
            float d3 = bbox[base + 3] * 0.2f;
            float h = ay2 - ay1;
            float w = ax2 - ax1;
            float cy = ay1 + 0.5f * h;
            float cx = ax1 + 0.5f * w;
            cy = cy + d0 * h;
            cx = cx + d1 * w;
            h = h * expf(d2);
            w = w * expf(d3);
            float y1 = cy - 0.5f * h;
            float x1 = cx - 0.5f * w;
            float y2 = y1 + h;
            float x2 = x1 + w;
            o0 = fminf(fmaxf(y1, 0.f), 1.f);
            o1 = fminf(fmaxf(x1, 0.f), 1.f);
            o2 = fminf(fmaxf(y2, 0.f), 1.f);
            o3 = fminf(fmaxf(x2, 0.f), 1.f);
        }
        int ob = (b * PRE + t) * 4;
        g_boxes[ob + 0] = o0;
        g_boxes[ob + 1] = o1;
        g_boxes[ob + 2] = o2;
        g_boxes[ob + 3] = o3;
        if (live) atomicOr(&g_alive[b * WROW + (t >> 5)], 1u << (t & 31));
    }
}

// ---------------- K7: windowed suppression matrix build ----------------
// Block (128 threads): rows [by*128, +128) vs cols [bx*64, +64), all < W.
__global__ void k_build() {
    int bx = blockIdx.x, by = blockIdx.y, b = blockIdx.z;
    if (bx * 64 + 64 <= by * 128) return;   // tile entirely j < i
    __shared__ float4 cb[64];
    __shared__ float  ca[64];
    int t = threadIdx.x;
    int j0 = bx * 64;
    const float4* boxes4 = (const float4*)g_boxes;
    if (t < 64) {
        float4 a = boxes4[b * PRE + j0 + t];
        cb[t] = a;
        ca[t] = (a.z - a.x) * (a.w - a.y);
    }
    __syncthreads();
    int i = by * 128 + t;
    float4 r = boxes4[b * PRE + i];
    float ra = (r.z - r.x) * (r.w - r.y);
    unsigned w0 = 0, w1 = 0;
    #pragma unroll 8
    for (int jj = 0; jj < 64; ++jj) {
        int j = j0 + jj;
        bool sup = false;
        if (j > i) {
            float4 c = cb[jj];
            float yy1 = fmaxf(r.x, c.x);
            float xx1 = fmaxf(r.y, c.y);
            float yy2 = fminf(r.z, c.z);
            float xx2 = fminf(r.w, c.w);
            float inter = fmaxf(yy2 - yy1, 0.f) * fmaxf(xx2 - xx1, 0.f);
            float u = ((ra + ca[jj]) - inter) + 1e-8f;
            if (inter >= 0.700007f * u)       sup = true;
            else if (inter <= 0.699993f * u)  sup = false;
            else                              sup = (inter / u >= 0.7f);
        }
        if (jj < 32) w0 |= ((unsigned)sup) << jj;
        else         w1 |= ((unsigned)sup) << (jj - 32);
    }
    uint2* rb = (uint2*)(g_mat + ((size_t)b * W + i) * MWORDS + bx * 2);
    *rb = make_uint2(w0, w1);
}

// ---------------- K8: speculative warp NMS, windowed + exact fallback ----------------
__global__ void k_nms_win(float* __restrict__ out) {
    __shared__ int cand_s[SPEC];
    __shared__ int s_picks[PROP];
    int b = blockIdx.x;
    int lane = threadIdx.x;
    const float4* boxes4 = (const float4*)g_boxes;

    for (int t = lane; t < PROP * 4; t += 32) out[b * PROP * 4 + t] = 0.f;

    // fast-path alive: words 0..63 (bits < W); lane owns word lane and 32+lane
    unsigned a0 = g_alive[b * WROW + lane];
    unsigned a1 = g_alive[b * WROW + 32 + lane];

    const unsigned* mat = g_mat + (size_t)b * W * MWORDS;

    int p = 0;
    for (;;) {
        unsigned bal0 = __ballot_sync(FULLM, a0 != 0u);
        unsigned bal1 = __ballot_sync(FULLM, a1 != 0u);

        int found = 0;
        unsigned bb = bal0;
        while (bb && found < SPEC) {
            int ln = __ffs(bb) - 1; bb &= bb - 1;
            unsigned w = __shfl_sync(FULLM, a0, ln);
            int base = ln * 32;
            while (w && found < SPEC) {
                cand_s[found++] = base + (__ffs(w) - 1);
                w &= w - 1;
            }
        }
        bb = bal1;
        while (bb && found < SPEC) {
            int ln = __ffs(bb) - 1; bb &= bb - 1;
            unsigned w = __shfl_sync(FULLM, a1, ln);
            int base = (32 + ln) * 32;
            while (w && found < SPEC) {
                cand_s[found++] = base + (__ffs(w) - 1);
                w &= w - 1;
            }
        }
        if (found == 0) break;   // window exhausted

        unsigned rw0[SPEC], rw1[SPEC];
        int cidx[SPEC];
        #pragma unroll
        for (int c = 0; c < SPEC; ++c) {
            cidx[c] = (c < found) ? cand_s[c] : -1;
            if (cidx[c] >= 0) {
                const unsigned* row = mat + (size_t)cidx[c] * MWORDS;
                rw0[c] = row[lane];
                rw1[c] = row[32 + lane];
            }
        }

        #pragma unroll
        for (int c = 0; c < SPEC; ++c) {
            if (cidx[c] < 0 || p >= PROP) continue;
            int i = cidx[c];
            int hi = i >> 10;                 // 0 -> a0, 1 -> a1
            int owner = (i >> 5) & 31;
            unsigned word = __shfl_sync(FULLM, hi ? a1 : a0, owner);
            if (!((word >> (i & 31)) & 1u)) continue;
            if (lane == owner) {
                if (hi) a1 &= ~(1u << (i & 31));
                else    a0 &= ~(1u << (i & 31));
            }
            if (lane < 4)
                out[(b * PROP + p) * 4 + lane] = g_boxes[(b * PRE + i) * 4 + lane];
            if (lane == 0) s_picks[p] = i;
            a0 &= ~rw0[c];
            a1 &= ~rw1[c];
            ++p;
        }
        if (p >= PROP) break;
    }

    if (p >= PROP) return;

    // ============ exact fallback (dead in practice) ============
    __syncwarp();
    // high alive words 64..187 (bits W..6015); lane owns 64+k*32+lane
    unsigned ah[4];
    #pragma unroll
    for (int k = 0; k < 4; ++k)
        ah[k] = g_alive[b * WROW + 64 + k * 32 + lane];

    // fix up: suppress high bits by all accepted picks (exact IoU)
    for (int q = 0; q < p; ++q) {
        int ip = s_picks[q];
        float4 pb = boxes4[b * PRE + ip];
        float pa = (pb.z - pb.x) * (pb.w - pb.y);
        #pragma unroll
        for (int k = 0; k < 4; ++k) {
            unsigned wbits = ah[k];
            while (wbits) {
                int bit = __ffs(wbits) - 1; wbits &= wbits - 1;
                int j = (64 + k * 32 + lane) * 32 + bit;
                if (j < PRE && iou_ge07(pb, pa, boxes4[b * PRE + j]))
                    ah[k] &= ~(1u << bit);
            }
        }
    }

    // continue greedy NMS over remaining (all alive bits are >= W)
    while (p < PROP) {
        unsigned bl[4];
        #pragma unroll
        for (int k = 0; k < 4; ++k)
            bl[k] = __ballot_sync(FULLM, ah[k] != 0u);
        int i = -1;
        #pragma unroll
        for (int k = 0; k < 4; ++k) {
            if (i < 0 && bl[k]) {
                int ln = __ffs(bl[k]) - 1;
                unsigned w = __shfl_sync(FULLM, ah[k], ln);
                i = (64 + k * 32 + ln) * 32 + (__ffs(w) - 1);
            }
        }
        if (i < 0) break;
        if (lane < 4)
            out[(b * PROP + p) * 4 + lane] = g_boxes[(b * PRE + i) * 4 + lane];
        float4 pb = boxes4[b * PRE + i];
        float pa = (pb.z - pb.x) * (pb.w - pb.y);
        #pragma unroll
        for (int k = 0; k < 4; ++k) {
            unsigned wbits = ah[k];
            while (wbits) {
                int bit = __ffs(wbits) - 1; wbits &= wbits - 1;
                int j = (64 + k * 32 + lane) * 32 + bit;
                if (j < PRE && iou_ge07(pb, pa, boxes4[b * PRE + j]))
                    ah[k] &= ~(1u << bit);
            }
        }
        // self bit (iou==1) is cleared by the loop above
        ++p;
    }
}

// ---------------- launch ----------------
extern "C" void kernel_launch(void* const* d_in, const int* in_sizes, int n_in,
                              void* d_out, int out_size) {
    const float* probs   = (const float*)d_in[0];
    const float* bbox    = (const float*)d_in[1];
    const float* anchors = (const float*)d_in[2];
    float* out = (float*)d_out;
    (void)in_sizes; (void)n_in; (void)out_size;

    cudaFuncSetAttribute(k_sortbox, cudaFuncAttributeMaxDynamicSharedMemorySize,
                         CAP * (int)sizeof(unsigned long long));

    k_zero<<<512, 256>>>();

    dim3 gridN(256, BATCH);
    k_score_hist<<<gridN, 256>>>(probs);
    k_findbin1<<<BATCH, 256>>>();
    k_hist2<<<gridN, 256>>>();
    k_findbin2<<<BATCH, 256>>>();
    k_compact<<<gridN, 256>>>();
    k_sortbox<<<BATCH, 1024, CAP * sizeof(unsigned long long)>>>(bbox, anchors);

    dim3 gridB(W / 64, W / 128, BATCH);
    k_build<<<gridB, 128>>>();

    k_nms_win<<<BATCH, 32>>>(out);
}

// round 6
// speedup vs baseline: 7.9321x; 1.1647x over previous
#include <cuda_runtime.h>
#include <cstdint>

#define BATCH 8
#define NVAL  261888
#define PRE   6000
#define CAP   8192
#define WROW  192          // alive words allocated per batch (188 used)
#define PROP  1000
#define W     2048         // NMS fast-path window (candidates)
#define MWORDS 64          // matrix row words (W/32)
#define SPEC  16           // speculative picks per round
#define FULLM 0xFFFFFFFFu

// ---------------- scratch (static device globals; no allocation) ----------------
__device__ unsigned           g_u[BATCH * NVAL];
__device__ unsigned           g_hist1[BATCH * 65536];
__device__ unsigned           g_b1[BATCH];
__device__ int                g_candcnt[BATCH];
__device__ unsigned long long g_cand[BATCH * CAP];
__device__ float              g_boxes[BATCH * PRE * 4];
__device__ unsigned           g_alive[BATCH * WROW];
__device__ unsigned           g_mat[(size_t)BATCH * W * MWORDS];   // 4 MB

__device__ __forceinline__ unsigned flip_f(float f) {
    unsigned b = __float_as_uint(f);
    unsigned mask = (unsigned)((int)b >> 31) | 0x80000000u;
    return b ^ mask;
}
__device__ __forceinline__ float unflip_f(unsigned u) {
    unsigned mask = (u >> 31) ? 0x80000000u : 0xFFFFFFFFu;
    return __uint_as_float(u ^ mask);
}

// exact reference-order IoU >= 0.7 test (slow path)
__device__ __forceinline__ bool iou_ge07(float4 a, float fa, float4 c) {
    float yy1 = fmaxf(a.x, c.x);
    float xx1 = fmaxf(a.y, c.y);
    float yy2 = fminf(a.z, c.z);
    float xx2 = fminf(a.w, c.w);
    float inter = fmaxf(yy2 - yy1, 0.f) * fmaxf(xx2 - xx1, 0.f);
    float ca = (c.z - c.x) * (c.w - c.y);
    float u = ((fa + ca) - inter) + 1e-8f;
    return inter / u >= 0.7f;
}

// ---------------- K0: zero scratch ----------------
__global__ void k_zero() {
    int total = BATCH * 65536;
    for (int i = blockIdx.x * blockDim.x + threadIdx.x; i < total;
         i += gridDim.x * blockDim.x)
        g_hist1[i] = 0;
    int gid = blockIdx.x * blockDim.x + threadIdx.x;
    if (gid < BATCH) g_candcnt[gid] = 0;
    if (gid < BATCH * WROW) g_alive[gid] = 0u;
}

// ---------------- K1: flip scores, hist of high 16 bits ----------------
__global__ void k_score_hist(const float* __restrict__ probs) {
    int b = blockIdx.y;
    const float2* p2 = (const float2*)probs;
    for (int n = blockIdx.x * blockDim.x + threadIdx.x; n < NVAL;
         n += gridDim.x * blockDim.x) {
        float s = p2[b * NVAL + n].y;
        unsigned u = flip_f(s);
        g_u[b * NVAL + n] = u;
        atomicAdd(&g_hist1[b * 65536 + (u >> 16)], 1u);
    }
}

// ---------------- K2: find high-16 bin containing rank PRE ----------------
__global__ void k_findbin1() {
    __shared__ unsigned part[256];
    int b = blockIdx.x;
    const unsigned* hist = g_hist1 + b * 65536;
    unsigned s = 0;
    int base = threadIdx.x * 256;
    for (int i = 0; i < 256; ++i) s += hist[base + i];
    part[threadIdx.x] = s;
    __syncthreads();
    if (threadIdx.x == 0) {
        unsigned acc = 0;
        for (int t = 255; t >= 0; --t) {
            if (acc + part[t] >= (unsigned)PRE) {
                for (int bin = t * 256 + 255; bin >= t * 256; --bin) {
                    unsigned h = hist[bin];
                    if (acc + h >= (unsigned)PRE) {
                        g_b1[b] = (unsigned)bin;
                        return;
                    }
                    acc += h;
                }
            }
            acc += part[t];
        }
        g_b1[b] = 0;
    }
}

// ---------------- K3: compact candidates (u >= b1<<16, superset of top-PRE) ----
__global__ void k_compact() {
    int b = blockIdx.y;
    unsigned T = g_b1[b] << 16;
    for (int n = blockIdx.x * blockDim.x + threadIdx.x; n < NVAL;
         n += gridDim.x * blockDim.x) {
        unsigned u = g_u[b * NVAL + n];
        if (u >= T) {
            int pos = atomicAdd(&g_candcnt[b], 1);
            if (pos < CAP)
                g_cand[b * CAP + pos] =
                    ((unsigned long long)u << 32) | (unsigned)(~(unsigned)n);
        }
    }
}

// ---------------- K4: register-assisted bitonic sort (desc) + box transform ----
__global__ void k_sortbox(const float* __restrict__ bbox,
                          const float* __restrict__ anchors) {
    extern __shared__ unsigned long long sk[];   // 8192 keys = 64 KB
    int b = blockIdx.x;
    int tid = threadIdx.x;
    int cnt = g_candcnt[b];
    if (cnt > CAP) cnt = CAP;
    for (int i = tid; i < CAP; i += 1024)
        sk[i] = (i < cnt) ? g_cand[b * CAP + i] : 0ULL;
    __syncthreads();

    int base = tid * 8;
    for (int k = 2; k <= CAP; k <<= 1) {
        // smem phases j >= 8
        for (int j = k >> 1; j >= 8; j >>= 1) {
            for (int i = tid; i < CAP; i += 1024) {
                int l = i ^ j;
                if (l > i) {
                    unsigned long long a = sk[i], c = sk[l];
                    bool seg = ((i & k) == 0);
                    if (seg ? (a < c) : (a > c)) { sk[i] = c; sk[l] = a; }
                }
            }
            __syncthreads();
        }
        // register phases j = 4,2,1 (within thread's 8 consecutive keys)
        {
            unsigned long long e[8];
            #pragma unroll
            for (int m = 0; m < 8; ++m) e[m] = sk[base + m];
            #pragma unroll
            for (int j = 4; j >= 1; j >>= 1) {
                if (j <= (k >> 1)) {
                    #pragma unroll
                    for (int m = 0; m < 8; ++m) {
                        int i = base + m, l = i ^ j;
                        if (l > i) {
                            int lm = m ^ j;
                            bool seg = ((i & k) == 0);
                            unsigned long long a = e[m], c = e[lm];
                            if (seg ? (a < c) : (a > c)) { e[m] = c; e[lm] = a; }
                        }
                    }
                }
            }
            #pragma unroll
            for (int m = 0; m < 8; ++m) sk[base + m] = e[m];
            __syncthreads();
        }
    }

    for (int t0 = 0; t0 < PRE; t0 += 1024) {
        int t = t0 + tid;
        bool inb = (t < PRE);
        unsigned long long key = inb ? sk[t] : 0ULL;
        unsigned u = (unsigned)(key >> 32);
        unsigned idx = ~((unsigned)key);
        float o0 = 0.f, o1 = 0.f, o2 = 0.f, o3 = 0.f;
        bool live = false;
        if (inb && key != 0ULL && idx < (unsigned)NVAL) {
            float score = unflip_f(u);
            live = (score >= 0.5f);
            int basei = (b * NVAL + (int)idx) * 4;
            float ay1 = anchors[basei + 0];
            float ax1 = anchors[basei + 1];
            float ay2 = anchors[basei + 2];
            float ax2 = anchors[basei + 3];
            float d0 = bbox[basei + 0] * 0.1f;
            float d1 = bbox[basei + 1] * 0.1f;
            float d2 = bbox[basei + 2] * 0.2f;
            float d3 = bbox[basei + 3] * 0.2f;
            float h = ay2 - ay1;
            float w = ax2 - ax1;
            float cy = ay1 + 0.5f * h;
            float cx = ax1 + 0.5f * w;
            cy = cy + d0 * h;
            cx = cx + d1 * w;
            h = h * expf(d2);
            w = w * expf(d3);
            float y1 = cy - 0.5f * h;
            float x1 = cx - 0.5f * w;
            float y2 = y1 + h;
            float x2 = x1 + w;
            o0 = fminf(fmaxf(y1, 0.f), 1.f);
            o1 = fminf(fmaxf(x1, 0.f), 1.f);
            o2 = fminf(fmaxf(y2, 0.f), 1.f);
            o3 = fminf(fmaxf(x2, 0.f), 1.f);
        }
        if (inb) {
            int ob = (b * PRE + t) * 4;
            g_boxes[ob + 0] = o0;
            g_boxes[ob + 1] = o1;
            g_boxes[ob + 2] = o2;
            g_boxes[ob + 3] = o3;
        }
        unsigned bal = __ballot_sync(FULLM, live);
        if ((tid & 31) == 0 && t < PRE)
            g_alive[b * WROW + (t >> 5)] = bal;
    }
}

// ---------------- K5: windowed suppression matrix build ----------------
__global__ void k_build() {
    int bx = blockIdx.x, by = blockIdx.y, b = blockIdx.z;
    if (bx * 64 + 64 <= by * 128) return;   // tile entirely j < i
    __shared__ float4 cb[64];
    __shared__ float  ca[64];
    int t = threadIdx.x;
    int j0 = bx * 64;
    const float4* boxes4 = (const float4*)g_boxes;
    if (t < 64) {
        float4 a = boxes4[b * PRE + j0 + t];
        cb[t] = a;
        ca[t] = (a.z - a.x) * (a.w - a.y);
    }
    __syncthreads();
    int i = by * 128 + t;
    float4 r = boxes4[b * PRE + i];
    float ra = (r.z - r.x) * (r.w - r.y);
    unsigned w0 = 0, w1 = 0;
    #pragma unroll 8
    for (int jj = 0; jj < 64; ++jj) {
        int j = j0 + jj;
        bool sup = false;
        if (j > i) {
            float4 c = cb[jj];
            float yy1 = fmaxf(r.x, c.x);
            float xx1 = fmaxf(r.y, c.y);
            float yy2 = fminf(r.z, c.z);
            float xx2 = fminf(r.w, c.w);
            float inter = fmaxf(yy2 - yy1, 0.f) * fmaxf(xx2 - xx1, 0.f);
            float u = ((ra + ca[jj]) - inter) + 1e-8f;
            if (inter >= 0.700007f * u)       sup = true;
            else if (inter <= 0.699993f * u)  sup = false;
            else                              sup = (inter / u >= 0.7f);
        }
        if (jj < 32) w0 |= ((unsigned)sup) << jj;
        else         w1 |= ((unsigned)sup) << (jj - 32);
    }
    uint2* rb = (uint2*)(g_mat + ((size_t)b * W + i) * MWORDS + bx * 2);
    *rb = make_uint2(w0, w1);
}

// ---------------- K6: frontier NMS (one warp per batch) + exact fallback ------
__global__ void k_nms_fast(float* __restrict__ out) {
    __shared__ int s_picks[PROP];
    int b = blockIdx.x;
    int lane = threadIdx.x;
    const float4* boxes4 = (const float4*)g_boxes;

    for (int t = lane; t < PROP * 4; t += 32) out[b * PROP * 4 + t] = 0.f;

    // window alive: lane owns word lane (a0) and 32+lane (a1)
    unsigned a0 = g_alive[b * WROW + lane];
    unsigned a1 = g_alive[b * WROW + 32 + lane];
    const unsigned* mat = g_mat + (size_t)b * W * MWORDS;

    int p = 0;
    while (p < PROP) {
        unsigned bal0 = __ballot_sync(FULLM, a0 != 0u);
        unsigned bal1 = __ballot_sync(FULLM, a1 != 0u);
        if (!bal0 && !bal1) break;

        // frontier words F, F2 (first two nonzero word indices)
        int F, F2 = -1;
        unsigned bb0 = bal0, bb1 = bal1;
        if (bb0) { F = __ffs(bb0) - 1; bb0 &= bb0 - 1; }
        else     { F = 32 + __ffs(bb1) - 1; bb1 &= bb1 - 1; }
        if (bb0)      F2 = __ffs(bb0) - 1;
        else if (bb1) F2 = 32 + __ffs(bb1) - 1;

        unsigned w0 = __shfl_sync(FULLM, (F < 32) ? a0 : a1, F & 31);
        unsigned w1 = (F2 >= 0)
                      ? __shfl_sync(FULLM, (F2 < 32) ? a0 : a1, F2 & 31) : 0u;

        // extract up to SPEC candidates from the two frontier words
        int cand[SPEC];
        int found = 0;
        unsigned t = w0;
        while (t && found < SPEC) { int bit = __ffs(t) - 1; t &= t - 1;
                                    cand[found++] = F * 32 + bit; }
        t = w1;
        while (t && found < SPEC) { int bit = __ffs(t) - 1; t &= t - 1;
                                    cand[found++] = F2 * 32 + bit; }

        // batch-load candidate rows (distributed: lane holds words lane, 32+lane)
        unsigned rw0[SPEC], rw1[SPEC];
        #pragma unroll
        for (int c = 0; c < SPEC; ++c) {
            if (c < found) {
                const unsigned* row = mat + (size_t)cand[c] * MWORDS;
                rw0[c] = row[lane];
                rw1[c] = row[32 + lane];
            } else { rw0[c] = 0; rw1[c] = 0; }
        }

        // pre-extract each row's frontier words (independent shfls, pipelined)
        unsigned fw0[SPEC], fw1[SPEC];
        #pragma unroll
        for (int c = 0; c < SPEC; ++c) {
            fw0[c] = __shfl_sync(FULLM, (F < 32) ? rw0[c] : rw1[c], F & 31);
            fw1[c] = (F2 >= 0)
                     ? __shfl_sync(FULLM, (F2 < 32) ? rw0[c] : rw1[c], F2 & 31) : 0u;
        }

        // uniform ALU accept chain on local frontier copies
        unsigned u0 = w0, u1 = w1;
        unsigned accmask = 0;
        #pragma unroll
        for (int c = 0; c < SPEC; ++c) {
            if (c >= found || p >= PROP) continue;
            int pos = cand[c];
            bool inF = ((pos >> 5) == F);
            unsigned cw = inF ? u0 : u1;
            if ((cw >> (pos & 31)) & 1u) {
                accmask |= 1u << c;
                if (lane == 0) s_picks[p] = pos;
                ++p;
                u0 &= ~fw0[c];
                u1 &= ~fw1[c];
                if (inF) u0 &= ~(1u << (pos & 31));
                else     u1 &= ~(1u << (pos & 31));
            }
        }

        // apply accepted rows + self-bits to distributed alive
        #pragma unroll
        for (int c = 0; c < SPEC; ++c) {
            if (accmask & (1u << c)) {
                a0 &= ~rw0[c];
                a1 &= ~rw1[c];
                int pos = cand[c];
                int wd = pos >> 5;
                if (lane == (wd & 31)) {
                    if (wd < 32) a0 &= ~(1u << (pos & 31));
                    else         a1 &= ~(1u << (pos & 31));
                }
            }
        }
    }

    // ============ exact fallback (dead in practice) ============
    if (p < PROP) {
        __syncwarp();
        unsigned ah[4];
        #pragma unroll
        for (int k = 0; k < 4; ++k)
            ah[k] = g_alive[b * WROW + 64 + k * 32 + lane];

        // suppress high bits by all accepted picks (exact IoU, reference order)
        for (int q = 0; q < p; ++q) {
            int ip = s_picks[q];
            float4 pb = boxes4[b * PRE + ip];
            float pa = (pb.z - pb.x) * (pb.w - pb.y);
            #pragma unroll
            for (int k = 0; k < 4; ++k) {
                unsigned wbits = ah[k];
                while (wbits) {
                    int bit = __ffs(wbits) - 1; wbits &= wbits - 1;
                    int j = (64 + k * 32 + lane) * 32 + bit;
                    if (j < PRE && iou_ge07(pb, pa, boxes4[b * PRE + j]))
                        ah[k] &= ~(1u << bit);
                }
            }
        }
        while (p < PROP) {
            unsigned bl[4];
            #pragma unroll
            for (int k = 0; k < 4; ++k)
                bl[k] = __ballot_sync(FULLM, ah[k] != 0u);
            int i = -1;
            #pragma unroll
            for (int k = 0; k < 4; ++k) {
                if (i < 0 && bl[k]) {
                    int ln = __ffs(bl[k]) - 1;
                    unsigned w = __shfl_sync(FULLM, ah[k], ln);
                    i = (64 + k * 32 + ln) * 32 + (__ffs(w) - 1);
                }
            }
            if (i < 0) break;
            if (lane == 0) s_picks[p] = i;
            ++p;
            float4 pb = boxes4[b * PRE + i];
            float pa = (pb.z - pb.x) * (pb.w - pb.y);
            #pragma unroll
            for (int k = 0; k < 4; ++k) {
                unsigned wbits = ah[k];
                while (wbits) {
                    int bit = __ffs(wbits) - 1; wbits &= wbits - 1;
                    int j = (64 + k * 32 + lane) * 32 + bit;
                    if (j < PRE && iou_ge07(pb, pa, boxes4[b * PRE + j]))
                        ah[k] &= ~(1u << bit);
                }
            }
        }
    }

    // parallel output emit
    __syncwarp();
    float4* out4 = (float4*)out;
    for (int q = lane; q < p; q += 32)
        out4[b * PROP + q] = boxes4[b * PRE + s_picks[q]];
}

// ---------------- launch ----------------
extern "C" void kernel_launch(void* const* d_in, const int* in_sizes, int n_in,
                              void* d_out, int out_size) {
    const float* probs   = (const float*)d_in[0];
    const float* bbox    = (const float*)d_in[1];
    const float* anchors = (const float*)d_in[2];
    float* out = (float*)d_out;
    (void)in_sizes; (void)n_in; (void)out_size;

    cudaFuncSetAttribute(k_sortbox, cudaFuncAttributeMaxDynamicSharedMemorySize,
                         CAP * (int)sizeof(unsigned long long));

    k_zero<<<512, 256>>>();

    dim3 gridN(256, BATCH);
    k_score_hist<<<gridN, 256>>>(probs);
    k_findbin1<<<BATCH, 256>>>();
    k_compact<<<gridN, 256>>>();
    k_sortbox<<<BATCH, 1024, CAP * sizeof(unsigned long long)>>>(bbox, anchors);

    dim3 gridB(W / 64, W / 128, BATCH);
    k_build<<<gridB, 128>>>();

    k_nms_fast<<<BATCH, 32>>>(out);
}

// round 7
// speedup vs baseline: 8.7056x; 1.0975x over previous
#include <cuda_runtime.h>
#include <cstdint>
#include <cub/block/block_radix_sort.cuh>

#define BATCH 8
#define NVAL  261888
#define PRE   6000
#define CAP   8192
#define WROW  192          // alive words allocated per batch (188 used)
#define PROP  1000
#define W     2048         // NMS fast-path window (candidates)
#define MWORDS 64          // matrix row words (W/32)
#define SPEC  16           // speculative picks per round
#define FULLM 0xFFFFFFFFu

#define SORT_THREADS 512
#define SORT_ITEMS   16    // 512*16 = 8192

// ---------------- scratch (static device globals; no allocation) ----------------
__device__ unsigned           g_u[BATCH * NVAL];
__device__ unsigned           g_hist1[BATCH * 65536];
__device__ unsigned           g_b1[BATCH];
__device__ int                g_candcnt[BATCH];
__device__ unsigned long long g_cand[BATCH * CAP];
__device__ float              g_boxes[BATCH * PRE * 4];
__device__ unsigned           g_alive[BATCH * WROW];
__device__ unsigned           g_mat[(size_t)BATCH * W * MWORDS];   // 4 MB

__device__ __forceinline__ unsigned flip_f(float f) {
    unsigned b = __float_as_uint(f);
    unsigned mask = (unsigned)((int)b >> 31) | 0x80000000u;
    return b ^ mask;
}
__device__ __forceinline__ float unflip_f(unsigned u) {
    unsigned mask = (u >> 31) ? 0x80000000u : 0xFFFFFFFFu;
    return __uint_as_float(u ^ mask);
}

// exact reference-order IoU >= 0.7 test (slow path)
__device__ __forceinline__ bool iou_ge07(float4 a, float fa, float4 c) {
    float yy1 = fmaxf(a.x, c.x);
    float xx1 = fmaxf(a.y, c.y);
    float yy2 = fminf(a.z, c.z);
    float xx2 = fminf(a.w, c.w);
    float inter = fmaxf(yy2 - yy1, 0.f) * fmaxf(xx2 - xx1, 0.f);
    float ca = (c.z - c.x) * (c.w - c.y);
    float u = ((fa + ca) - inter) + 1e-8f;
    return inter / u >= 0.7f;
}

// ---------------- K0: zero scratch ----------------
__global__ void k_zero() {
    int total = BATCH * 65536;
    for (int i = blockIdx.x * blockDim.x + threadIdx.x; i < total;
         i += gridDim.x * blockDim.x)
        g_hist1[i] = 0;
    int gid = blockIdx.x * blockDim.x + threadIdx.x;
    if (gid < BATCH) g_candcnt[gid] = 0;
    if (gid < BATCH * WROW) g_alive[gid] = 0u;
}

// ---------------- K1: flip scores, hist of high 16 bits ----------------
__global__ void k_score_hist(const float* __restrict__ probs) {
    int b = blockIdx.y;
    const float2* p2 = (const float2*)probs;
    for (int n = blockIdx.x * blockDim.x + threadIdx.x; n < NVAL;
         n += gridDim.x * blockDim.x) {
        float s = p2[b * NVAL + n].y;
        unsigned u = flip_f(s);
        g_u[b * NVAL + n] = u;
        atomicAdd(&g_hist1[b * 65536 + (u >> 16)], 1u);
    }
}

// ---------------- K2: find high-16 bin containing rank PRE ----------------
__global__ void k_findbin1() {
    __shared__ unsigned part[256];
    int b = blockIdx.x;
    const unsigned* hist = g_hist1 + b * 65536;
    unsigned s = 0;
    int base = threadIdx.x * 256;
    for (int i = 0; i < 256; ++i) s += hist[base + i];
    part[threadIdx.x] = s;
    __syncthreads();
    if (threadIdx.x == 0) {
        unsigned acc = 0;
        for (int t = 255; t >= 0; --t) {
            if (acc + part[t] >= (unsigned)PRE) {
                for (int bin = t * 256 + 255; bin >= t * 256; --bin) {
                    unsigned h = hist[bin];
                    if (acc + h >= (unsigned)PRE) {
                        g_b1[b] = (unsigned)bin;
                        return;
                    }
                    acc += h;
                }
            }
            acc += part[t];
        }
        g_b1[b] = 0;
    }
}

// ---------------- K3: compact candidates (warp-aggregated atomics) ----------
__global__ void k_compact() {
    int b = blockIdx.y;
    unsigned T = g_b1[b] << 16;
    int lane = threadIdx.x & 31;
    int stride = gridDim.x * blockDim.x;
    int start = blockIdx.x * blockDim.x + threadIdx.x;
    int iters = (NVAL + stride - 1) / stride;
    for (int it = 0; it < iters; ++it) {
        int n = start + it * stride;
        unsigned u = 0;
        bool pass = false;
        if (n < NVAL) {
            u = g_u[b * NVAL + n];
            pass = (u >= T);
        }
        unsigned bal = __ballot_sync(FULLM, pass);
        if (!bal) continue;
        int leader = __ffs(bal) - 1;
        int base = 0;
        if (lane == leader)
            base = atomicAdd(&g_candcnt[b], __popc(bal));
        base = __shfl_sync(FULLM, base, leader);
        if (pass) {
            int pos = base + __popc(bal & ((1u << lane) - 1u));
            if (pos < CAP)
                g_cand[b * CAP + pos] =
                    ((unsigned long long)u << 18) |
                    (unsigned long long)(0x3FFFFu - (unsigned)n);
        }
    }
}

// ---------------- K4: CUB radix sort (desc, 50 bits) + box transform ----------
typedef cub::BlockRadixSort<unsigned long long, SORT_THREADS, SORT_ITEMS> BRS;

__global__ void k_sortbox(const float* __restrict__ bbox,
                          const float* __restrict__ anchors) {
    extern __shared__ char smem_raw[];
    typename BRS::TempStorage* temp =
        reinterpret_cast<typename BRS::TempStorage*>(smem_raw);
    unsigned long long* skeys =
        reinterpret_cast<unsigned long long*>(smem_raw);   // reused after sort

    int b = blockIdx.x;
    int tid = threadIdx.x;
    int cnt = g_candcnt[b];
    if (cnt > CAP) cnt = CAP;

    unsigned long long keys[SORT_ITEMS];
    #pragma unroll
    for (int m = 0; m < SORT_ITEMS; ++m) {
        int i = tid * SORT_ITEMS + m;
        keys[m] = (i < cnt) ? g_cand[b * CAP + i] : 0ULL;
    }

    BRS(*temp).SortDescending(keys, 0, 50);
    __syncthreads();

    #pragma unroll
    for (int m = 0; m < SORT_ITEMS; ++m)
        skeys[tid * SORT_ITEMS + m] = keys[m];
    __syncthreads();

    for (int t0 = 0; t0 < PRE; t0 += SORT_THREADS) {
        int t = t0 + tid;
        bool inb = (t < PRE);
        unsigned long long key = inb ? skeys[t] : 0ULL;
        unsigned u = (unsigned)(key >> 18);
        unsigned idx = 0x3FFFFu - (unsigned)(key & 0x3FFFFu);
        float o0 = 0.f, o1 = 0.f, o2 = 0.f, o3 = 0.f;
        bool live = false;
        if (inb && key != 0ULL && idx < (unsigned)NVAL) {
            float score = unflip_f(u);
            live = (score >= 0.5f);
            int basei = (b * NVAL + (int)idx) * 4;
            float ay1 = anchors[basei + 0];
            float ax1 = anchors[basei + 1];
            float ay2 = anchors[basei + 2];
            float ax2 = anchors[basei + 3];
            float d0 = bbox[basei + 0] * 0.1f;
            float d1 = bbox[basei + 1] * 0.1f;
            float d2 = bbox[basei + 2] * 0.2f;
            float d3 = bbox[basei + 3] * 0.2f;
            float h = ay2 - ay1;
            float w = ax2 - ax1;
            float cy = ay1 + 0.5f * h;
            float cx = ax1 + 0.5f * w;
            cy = cy + d0 * h;
            cx = cx + d1 * w;
            h = h * expf(d2);
            w = w * expf(d3);
            float y1 = cy - 0.5f * h;
            float x1 = cx - 0.5f * w;
            float y2 = y1 + h;
            float x2 = x1 + w;
            o0 = fminf(fmaxf(y1, 0.f), 1.f);
            o1 = fminf(fmaxf(x1, 0.f), 1.f);
            o2 = fminf(fmaxf(y2, 0.f), 1.f);
            o3 = fminf(fmaxf(x2, 0.f), 1.f);
        }
        if (inb) {
            int ob = (b * PRE + t) * 4;
            g_boxes[ob + 0] = o0;
            g_boxes[ob + 1] = o1;
            g_boxes[ob + 2] = o2;
            g_boxes[ob + 3] = o3;
        }
        unsigned bal = __ballot_sync(FULLM, live);
        if ((tid & 31) == 0 && t < PRE)
            g_alive[b * WROW + (t >> 5)] = bal;
    }
}

// ---------------- K5: windowed suppression matrix build ----------------
__global__ void k_build() {
    int bx = blockIdx.x, by = blockIdx.y, b = blockIdx.z;
    if (bx * 64 + 64 <= by * 128) return;   // tile entirely j < i
    __shared__ float4 cb[64];
    __shared__ float  ca[64];
    int t = threadIdx.x;
    int j0 = bx * 64;
    const float4* boxes4 = (const float4*)g_boxes;
    if (t < 64) {
        float4 a = boxes4[b * PRE + j0 + t];
        cb[t] = a;
        ca[t] = (a.z - a.x) * (a.w - a.y);
    }
    __syncthreads();
    int i = by * 128 + t;
    float4 r = boxes4[b * PRE + i];
    float ra = (r.z - r.x) * (r.w - r.y);
    unsigned w0 = 0, w1 = 0;
    #pragma unroll 8
    for (int jj = 0; jj < 64; ++jj) {
        int j = j0 + jj;
        bool sup = false;
        if (j > i) {
            float4 c = cb[jj];
            float yy1 = fmaxf(r.x, c.x);
            float xx1 = fmaxf(r.y, c.y);
            float yy2 = fminf(r.z, c.z);
            float xx2 = fminf(r.w, c.w);
            float inter = fmaxf(yy2 - yy1, 0.f) * fmaxf(xx2 - xx1, 0.f);
            float u = ((ra + ca[jj]) - inter) + 1e-8f;
            if (inter >= 0.700007f * u)       sup = true;
            else if (inter <= 0.699993f * u)  sup = false;
            else                              sup = (inter / u >= 0.7f);
        }
        if (jj < 32) w0 |= ((unsigned)sup) << jj;
        else         w1 |= ((unsigned)sup) << (jj - 32);
    }
    uint2* rb = (uint2*)(g_mat + ((size_t)b * W + i) * MWORDS + bx * 2);
    *rb = make_uint2(w0, w1);
}

// ---------------- K6: frontier NMS (one warp per batch) + exact fallback ------
__global__ void k_nms_fast(float* __restrict__ out) {
    __shared__ int s_picks[PROP];
    int b = blockIdx.x;
    int lane = threadIdx.x;
    const float4* boxes4 = (const float4*)g_boxes;

    for (int t = lane; t < PROP * 4; t += 32) out[b * PROP * 4 + t] = 0.f;

    // window alive: lane owns word lane (a0) and 32+lane (a1)
    unsigned a0 = g_alive[b * WROW + lane];
    unsigned a1 = g_alive[b * WROW + 32 + lane];
    const unsigned* mat = g_mat + (size_t)b * W * MWORDS;

    int p = 0;
    while (p < PROP) {
        unsigned bal0 = __ballot_sync(FULLM, a0 != 0u);
        unsigned bal1 = __ballot_sync(FULLM, a1 != 0u);
        if (!bal0 && !bal1) break;

        // frontier words F, F2 (first two nonzero word indices)
        int F, F2 = -1;
        unsigned bb0 = bal0, bb1 = bal1;
        if (bb0) { F = __ffs(bb0) - 1; bb0 &= bb0 - 1; }
        else     { F = 32 + __ffs(bb1) - 1; bb1 &= bb1 - 1; }
        if (bb0)      F2 = __ffs(bb0) - 1;
        else if (bb1) F2 = 32 + __ffs(bb1) - 1;

        unsigned w0 = __shfl_sync(FULLM, (F < 32) ? a0 : a1, F & 31);
        unsigned w1 = (F2 >= 0)
                      ? __shfl_sync(FULLM, (F2 < 32) ? a0 : a1, F2 & 31) : 0u;

        // extract up to SPEC candidates from the two frontier words
        int cand[SPEC];
        int found = 0;
        unsigned t = w0;
        while (t && found < SPEC) { int bit = __ffs(t) - 1; t &= t - 1;
                                    cand[found++] = F * 32 + bit; }
        t = w1;
        while (t && found < SPEC) { int bit = __ffs(t) - 1; t &= t - 1;
                                    cand[found++] = F2 * 32 + bit; }

        // batch-load candidate rows (distributed: lane holds words lane, 32+lane)
        unsigned rw0[SPEC], rw1[SPEC];
        #pragma unroll
        for (int c = 0; c < SPEC; ++c) {
            if (c < found) {
                const unsigned* row = mat + (size_t)cand[c] * MWORDS;
                rw0[c] = row[lane];
                rw1[c] = row[32 + lane];
            } else { rw0[c] = 0; rw1[c] = 0; }
        }

        // pre-extract each row's frontier words (independent shfls, pipelined)
        unsigned fw0[SPEC], fw1[SPEC];
        #pragma unroll
        for (int c = 0; c < SPEC; ++c) {
            fw0[c] = __shfl_sync(FULLM, (F < 32) ? rw0[c] : rw1[c], F & 31);
            fw1[c] = (F2 >= 0)
                     ? __shfl_sync(FULLM, (F2 < 32) ? rw0[c] : rw1[c], F2 & 31) : 0u;
        }

        // uniform ALU accept chain on local frontier copies
        unsigned u0 = w0, u1 = w1;
        unsigned accmask = 0;
        #pragma unroll
        for (int c = 0; c < SPEC; ++c) {
            if (c >= found || p >= PROP) continue;
            int pos = cand[c];
            bool inF = ((pos >> 5) == F);
            unsigned cw = inF ? u0 : u1;
            if ((cw >> (pos & 31)) & 1u) {
                accmask |= 1u << c;
                if (lane == 0) s_picks[p] = pos;
                ++p;
                u0 &= ~fw0[c];
                u1 &= ~fw1[c];
                if (inF) u0 &= ~(1u << (pos & 31));
                else     u1 &= ~(1u << (pos & 31));
            }
        }

        // apply accepted rows + self-bits to distributed alive
        #pragma unroll
        for (int c = 0; c < SPEC; ++c) {
            if (accmask & (1u << c)) {
                a0 &= ~rw0[c];
                a1 &= ~rw1[c];
                int pos = cand[c];
                int wd = pos >> 5;
                if (lane == (wd & 31)) {
                    if (wd < 32) a0 &= ~(1u << (pos & 31));
                    else         a1 &= ~(1u << (pos & 31));
                }
            }
        }
    }

    // ============ exact fallback (dead in practice) ============
    if (p < PROP) {
        __syncwarp();
        unsigned ah[4];
        #pragma unroll
        for (int k = 0; k < 4; ++k)
            ah[k] = g_alive[b * WROW + 64 + k * 32 + lane];

        // suppress high bits by all accepted picks (exact IoU, reference order)
        for (int q = 0; q < p; ++q) {
            int ip = s_picks[q];
            float4 pb = boxes4[b * PRE + ip];
            float pa = (pb.z - pb.x) * (pb.w - pb.y);
            #pragma unroll
            for (int k = 0; k < 4; ++k) {
                unsigned wbits = ah[k];
                while (wbits) {
                    int bit = __ffs(wbits) - 1; wbits &= wbits - 1;
                    int j = (64 + k * 32 + lane) * 32 + bit;
                    if (j < PRE && iou_ge07(pb, pa, boxes4[b * PRE + j]))
                        ah[k] &= ~(1u << bit);
                }
            }
        }
        while (p < PROP) {
            unsigned bl[4];
            #pragma unroll
            for (int k = 0; k < 4; ++k)
                bl[k] = __ballot_sync(FULLM, ah[k] != 0u);
            int i = -1;
            #pragma unroll
            for (int k = 0; k < 4; ++k) {
                if (i < 0 && bl[k]) {
                    int ln = __ffs(bl[k]) - 1;
                    unsigned w = __shfl_sync(FULLM, ah[k], ln);
                    i = (64 + k * 32 + ln) * 32 + (__ffs(w) - 1);
                }
            }
            if (i < 0) break;
            if (lane == 0) s_picks[p] = i;
            ++p;
            float4 pb = boxes4[b * PRE + i];
            float pa = (pb.z - pb.x) * (pb.w - pb.y);
            #pragma unroll
            for (int k = 0; k < 4; ++k) {
                unsigned wbits = ah[k];
                while (wbits) {
                    int bit = __ffs(wbits) - 1; wbits &= wbits - 1;
                    int j = (64 + k * 32 + lane) * 32 + bit;
                    if (j < PRE && iou_ge07(pb, pa, boxes4[b * PRE + j]))
                        ah[k] &= ~(1u << bit);
                }
            }
        }
    }

    // parallel output emit
    __syncwarp();
    float4* out4 = (float4*)out;
    for (int q = lane; q < p; q += 32)
        out4[b * PROP + q] = boxes4[b * PRE + s_picks[q]];
}

// ---------------- launch ----------------
extern "C" void kernel_launch(void* const* d_in, const int* in_sizes, int n_in,
                              void* d_out, int out_size) {
    const float* probs   = (const float*)d_in[0];
    const float* bbox    = (const float*)d_in[1];
    const float* anchors = (const float*)d_in[2];
    float* out = (float*)d_out;
    (void)in_sizes; (void)n_in; (void)out_size;

    size_t sort_smem = sizeof(typename BRS::TempStorage);
    size_t keys_smem = (size_t)CAP * sizeof(unsigned long long);
    if (keys_smem > sort_smem) sort_smem = keys_smem;
    cudaFuncSetAttribute(k_sortbox, cudaFuncAttributeMaxDynamicSharedMemorySize,
                         (int)sort_smem);

    k_zero<<<512, 256>>>();

    dim3 gridN(256, BATCH);
    k_score_hist<<<gridN, 256>>>(probs);
    k_findbin1<<<BATCH, 256>>>();
    k_compact<<<gridN, 256>>>();
    k_sortbox<<<BATCH, SORT_THREADS, sort_smem>>>(bbox, anchors);

    dim3 gridB(W / 64, W / 128, BATCH);
    k_build<<<gridB, 128>>>();

    k_nms_fast<<<BATCH, 32>>>(out);
}